// round 9
// baseline (speedup 1.0000x reference)
#include <cuda_runtime.h>
#include <cuda_fp16.h>

// Problem constants
#define GRID_HW 512
#define HWO     (GRID_HW * GRID_HW)          // 262144 = 2^18
#define NPIX    (4 * HWO)                    // 1048576 = 2^20
#define FEAT    16

// Level sizes (square textures)
#define W1 1024
#define W2 512
#define W3 256
#define W4 128
#define N1 (W1 * W1)
#define N2 (W2 * W2)
#define N3 (W3 * W3)
#define N4 (W4 * W4)

// Feature-interleaved fp16 packed textures: one texel = 16 halfs = 32B record
// stored as 2 x uint4 (features 0-7, 8-15). 42.5 MB total -> L2 resident.
__device__ __align__(16) static uint4 g_p1[N1 * 2];   // 32 MB
__device__ __align__(16) static uint4 g_p2[N2 * 2];   //  8 MB
__device__ __align__(16) static uint4 g_p3[N3 * 2];   //  2 MB
__device__ __align__(16) static uint4 g_p4[N4 * 2];   //  0.5 MB

// Packed f32x2 helpers (Blackwell): FFMA2 reachable only via PTX.
#define PACK_F32X2(out, lo, hi) \
    asm("mov.b64 %0, {%1, %2};" : "=l"(out) : "r"(lo), "r"(hi))
#define FMA_F32X2(d, a, b, c) \
    asm("fma.rn.f32x2 %0, %1, %2, %3;" : "=l"(d) : "l"(a), "l"(b), "l"(c))
#define UNPACK_F32X2(lo, hi, in) \
    asm("mov.b64 {%0, %1}, %2;" : "=r"(lo), "=r"(hi) : "l"(in))

// ---------------------------------------------------------------------------
// Fused repack (R7 version — measured ~22us, near DRAM floor). src (F, H, W)
// fp32 channel-major -> dst AoS fp16 records. Two consecutive texels per
// thread: float2 loads per feature (coalesced), 64B contiguous stores.
// ---------------------------------------------------------------------------
__global__ void __launch_bounds__(256) repack_fused_kernel(
    const float* __restrict__ t1, const float* __restrict__ t2,
    const float* __restrict__ t3, const float* __restrict__ t4) {
    int idx = blockIdx.x * blockDim.x + threadIdx.x;   // texel pair index

    const float* src;
    uint4* dst;
    int pair, HW;
    const int H1 = N1 / 2, H2 = H1 + N2 / 2, H3 = H2 + N3 / 2, H4 = H3 + N4 / 2;
    if (idx < H1)      { src = t1; dst = g_p1; pair = idx;      HW = N1; }
    else if (idx < H2) { src = t2; dst = g_p2; pair = idx - H1; HW = N2; }
    else if (idx < H3) { src = t3; dst = g_p3; pair = idx - H2; HW = N3; }
    else if (idx < H4) { src = t4; dst = g_p4; pair = idx - H3; HW = N4; }
    else return;

    int lin = pair * 2;

    half2 r0[8], r1[8];
#pragma unroll
    for (int f = 0; f < 8; f++) {
        float2 a = __ldcs((const float2*)(src + (size_t)(2 * f)     * HW + lin));
        float2 b = __ldcs((const float2*)(src + (size_t)(2 * f + 1) * HW + lin));
        r0[f] = __floats2half2_rn(a.x, b.x);   // texel lin
        r1[f] = __floats2half2_rn(a.y, b.y);   // texel lin+1
    }
    uint4 o;
    o.x = *reinterpret_cast<unsigned*>(&r0[0]); o.y = *reinterpret_cast<unsigned*>(&r0[1]);
    o.z = *reinterpret_cast<unsigned*>(&r0[2]); o.w = *reinterpret_cast<unsigned*>(&r0[3]);
    dst[(size_t)lin * 2 + 0] = o;
    o.x = *reinterpret_cast<unsigned*>(&r0[4]); o.y = *reinterpret_cast<unsigned*>(&r0[5]);
    o.z = *reinterpret_cast<unsigned*>(&r0[6]); o.w = *reinterpret_cast<unsigned*>(&r0[7]);
    dst[(size_t)lin * 2 + 1] = o;
    o.x = *reinterpret_cast<unsigned*>(&r1[0]); o.y = *reinterpret_cast<unsigned*>(&r1[1]);
    o.z = *reinterpret_cast<unsigned*>(&r1[2]); o.w = *reinterpret_cast<unsigned*>(&r1[3]);
    dst[(size_t)lin * 2 + 2] = o;
    o.x = *reinterpret_cast<unsigned*>(&r1[4]); o.y = *reinterpret_cast<unsigned*>(&r1[5]);
    o.z = *reinterpret_cast<unsigned*>(&r1[6]); o.w = *reinterpret_cast<unsigned*>(&r1[7]);
    dst[(size_t)lin * 2 + 3] = o;
}

// ---------------------------------------------------------------------------
// Per-level phase A: compile-time W so row offsets strength-reduce to shifts.
// Issues this level's two LDG.128 (rows y0/y1 of this lane's x-side/half).
// ---------------------------------------------------------------------------
template <int W>
__device__ __forceinline__ void level_load(const uint4* __restrict__ base,
                                           float ix, float iy, int h, int side,
                                           uint4& u0, uint4& u1,
                                           float& wxs, half2& w0h, half2& w1h) {
    const float Wf = (float)W;
    float cx = fminf(fmaxf(ix, 0.0f), Wf - 1.0f);
    float cy = fminf(fmaxf(iy, 0.0f), Wf - 1.0f);
    float x0f = floorf(cx);
    float y0f = floorf(cy);
    float wx = cx - x0f;
    float wy = cy - y0f;
    int x0 = (int)x0f;
    int y0 = (int)y0f;
    int xs = side ? min(x0 + 1, W - 1) : x0;
    int y1 = min(y0 + 1, W - 1);

    wxs = side ? wx : (1.0f - wx);
    w0h = __float2half2_rn(1.0f - wy);
    w1h = __float2half2_rn(wy);

    u0 = __ldg(base + ((y0 * W + xs) * 2 + h));
    u1 = __ldg(base + ((y1 * W + xs) * 2 + h));
}

// ---------------------------------------------------------------------------
// Gather: one thread per (pixel, feature-half, x-side). t = p*4 + side*2 + h.
// Phase A: all 8 LDG.128 front-batched (MLP=8), derived-coordinate chain.
// Phase B: half2 row-fold per level; fp32 accumulate via packed fma.rn.f32x2
// (4 FFMA2 per level instead of 8 FFMA).
// Epilogue: shfl.xor(2) folds x-sides; side-0 lanes store 8 features.
// ---------------------------------------------------------------------------
__global__ void __launch_bounds__(256) gather_kernel(const float* __restrict__ grid,
                                                     float* __restrict__ out) {
    int t = blockIdx.x * blockDim.x + threadIdx.x;
    int p    = t >> 2;           // pixel 0..2^20-1
    int h    = t & 1;            // feature half
    int side = (t >> 1) & 1;     // x corner side

    float2 g = __ldg((const float2*)grid + p);

    // Unclamped level-1 coords; per-level derived by ix' = 0.5*ix - 0.25.
    float ix = ((g.x + 1.0f) * (float)W1 - 1.0f) * 0.5f;
    float iy = ((g.y + 1.0f) * (float)W1 - 1.0f) * 0.5f;

    uint4 u0[4], u1[4];
    half2 w0h[4], w1h[4];
    float wxs[4];

    level_load<W1>(g_p1, ix, iy, h, side, u0[0], u1[0], wxs[0], w0h[0], w1h[0]);
    ix = ix * 0.5f - 0.25f;  iy = iy * 0.5f - 0.25f;
    level_load<W2>(g_p2, ix, iy, h, side, u0[1], u1[1], wxs[1], w0h[1], w1h[1]);
    ix = ix * 0.5f - 0.25f;  iy = iy * 0.5f - 0.25f;
    level_load<W3>(g_p3, ix, iy, h, side, u0[2], u1[2], wxs[2], w0h[2], w1h[2]);
    ix = ix * 0.5f - 0.25f;  iy = iy * 0.5f - 0.25f;
    level_load<W4>(g_p4, ix, iy, h, side, u0[3], u1[3], wxs[3], w0h[3], w1h[3]);

    // Packed f32x2 accumulators: acc2[k] holds features (2k, 2k+1).
    unsigned long long acc2[4] = {0ull, 0ull, 0ull, 0ull};

#pragma unroll
    for (int L = 0; L < 4; L++) {
        const half2* v0 = reinterpret_cast<const half2*>(&u0[L]);
        const half2* v1 = reinterpret_cast<const half2*>(&u1[L]);
        unsigned wsb = __float_as_uint(wxs[L]);
        unsigned long long ws2;
        PACK_F32X2(ws2, wsb, wsb);
#pragma unroll
        for (int k = 0; k < 4; k++) {
            half2 tk = __hfma2(v1[k], w1h[L], __hmul2(v0[k], w0h[L]));
            float2 tf = __half22float2(tk);
            unsigned long long tf2;
            PACK_F32X2(tf2, __float_as_uint(tf.x), __float_as_uint(tf.y));
            FMA_F32X2(acc2[k], tf2, ws2, acc2[k]);
        }
    }

    // Unpack, fold x-sides via shfl.xor(2); side-0 lanes store.
    float acc[8];
#pragma unroll
    for (int k = 0; k < 4; k++) {
        unsigned lo, hi;
        UNPACK_F32X2(lo, hi, acc2[k]);
        acc[2 * k]     = __uint_as_float(lo);
        acc[2 * k + 1] = __uint_as_float(hi);
    }
#pragma unroll
    for (int j = 0; j < 8; j++)
        acc[j] += __shfl_xor_sync(0xffffffffu, acc[j], 2);

    if (side == 0) {
        int b  = p >> 18;        // batch
        int hw = p & (HWO - 1);
        // out layout: (B, F, Ho, Wo); this lane owns features 8h..8h+7
        size_t base = ((size_t)(b * FEAT + h * 8) << 18) | (unsigned)hw;
#pragma unroll
        for (int j = 0; j < 8; j++)
            __stcs(out + base + (size_t)j * HWO, acc[j]);  // streaming stores
    }
}

extern "C" void kernel_launch(void* const* d_in, const int* in_sizes, int n_in,
                              void* d_out, int out_size) {
    const float* x    = (const float*)d_in[0];   // (4, 512, 512, 2)
    const float* tex1 = (const float*)d_in[1];   // (16, 1024, 1024)
    const float* tex2 = (const float*)d_in[2];   // (16, 512, 512)
    const float* tex3 = (const float*)d_in[3];   // (16, 256, 256)
    const float* tex4 = (const float*)d_in[4];   // (16, 128, 128)
    float* out = (float*)d_out;                  // (4, 16, 512, 512)

    // Fused repack: all levels -> fp16 AoS records. Two texels per thread.
    const int total_pairs = (N1 + N2 + N3 + N4) / 2;   // 688,128
    repack_fused_kernel<<<(total_pairs + 255) / 256, 256>>>(tex1, tex2, tex3, tex4);

    // Gather + blend + sum levels. One thread per (pixel, half, side).
    gather_kernel<<<(4 * NPIX) / 256, 256>>>(x, out);
}

// round 10
// speedup vs baseline: 1.1173x; 1.1173x over previous
#include <cuda_runtime.h>
#include <cuda_fp16.h>

// Problem constants
#define GRID_HW 512
#define HWO     (GRID_HW * GRID_HW)          // 262144 = 2^18
#define NPIX    (4 * HWO)                    // 1048576 = 2^20
#define FEAT    16

// Level sizes (square textures)
#define W1 1024
#define W2 512
#define W3 256
#define W4 128
#define N1 (W1 * W1)
#define N2 (W2 * W2)
#define N3 (W3 * W3)
#define N4 (W4 * W4)

// Level 1: plain fp16 records (16 halfs = 32B per texel), 32 MB.
__device__ __align__(128) static uint4 g_p1[N1 * 2];
// Levels 2-4: x-pair entries: entry(y,x) = [rec(x) | rec(min(x+1,W-1))],
// 64B per texel, always 64B aligned -> 1 L1 wavefront per row access.
__device__ __align__(128) static uint4 g_q2[N2 * 4];  // 16 MB
__device__ __align__(128) static uint4 g_q3[N3 * 4];  //  4 MB
__device__ __align__(128) static uint4 g_q4[N4 * 4];  //  1 MB

// ---------------------------------------------------------------------------
// Fused repack. Range [0, H1): level-1 plain records, two texels per thread
// (R7 path, measured near DRAM floor). Ranges beyond: pair entries for
// levels 2-4, one even-x texel pair per thread producing entries x and x+1
// (8 contiguous STG.128 = 128B).
// ---------------------------------------------------------------------------
__global__ void __launch_bounds__(256) repack_fused_kernel(
    const float* __restrict__ t1, const float* __restrict__ t2,
    const float* __restrict__ t3, const float* __restrict__ t4) {
    int idx = blockIdx.x * blockDim.x + threadIdx.x;

    const int H1 = N1 / 2;
    const int P2 = H1 + N2 / 2, P3 = P2 + N3 / 2, P4 = P3 + N4 / 2;

    if (idx < H1) {
        // ----- Level 1: plain records, texel pair (R7 code) -----
        int lin = idx * 2;
        half2 r0[8], r1[8];
#pragma unroll
        for (int f = 0; f < 8; f++) {
            float2 a = __ldcs((const float2*)(t1 + (size_t)(2 * f)     * N1 + lin));
            float2 b = __ldcs((const float2*)(t1 + (size_t)(2 * f + 1) * N1 + lin));
            r0[f] = __floats2half2_rn(a.x, b.x);
            r1[f] = __floats2half2_rn(a.y, b.y);
        }
        uint4 o;
        o.x = *reinterpret_cast<unsigned*>(&r0[0]); o.y = *reinterpret_cast<unsigned*>(&r0[1]);
        o.z = *reinterpret_cast<unsigned*>(&r0[2]); o.w = *reinterpret_cast<unsigned*>(&r0[3]);
        g_p1[(size_t)lin * 2 + 0] = o;
        o.x = *reinterpret_cast<unsigned*>(&r0[4]); o.y = *reinterpret_cast<unsigned*>(&r0[5]);
        o.z = *reinterpret_cast<unsigned*>(&r0[6]); o.w = *reinterpret_cast<unsigned*>(&r0[7]);
        g_p1[(size_t)lin * 2 + 1] = o;
        o.x = *reinterpret_cast<unsigned*>(&r1[0]); o.y = *reinterpret_cast<unsigned*>(&r1[1]);
        o.z = *reinterpret_cast<unsigned*>(&r1[2]); o.w = *reinterpret_cast<unsigned*>(&r1[3]);
        g_p1[(size_t)lin * 2 + 2] = o;
        o.x = *reinterpret_cast<unsigned*>(&r1[4]); o.y = *reinterpret_cast<unsigned*>(&r1[5]);
        o.z = *reinterpret_cast<unsigned*>(&r1[6]); o.w = *reinterpret_cast<unsigned*>(&r1[7]);
        g_p1[(size_t)lin * 2 + 3] = o;
        return;
    }

    // ----- Levels 2-4: pair entries -----
    const float* src;
    uint4* dst;
    int e, W, HW;
    if (idx < P2)      { src = t2; dst = g_q2; e = idx - H1; W = W2; HW = N2; }
    else if (idx < P3) { src = t3; dst = g_q3; e = idx - P2; W = W3; HW = N3; }
    else if (idx < P4) { src = t4; dst = g_q4; e = idx - P3; W = W4; HW = N4; }
    else return;

    int y  = e / (W / 2);
    int x  = (e - y * (W / 2)) * 2;          // even x
    int lin = y * W + x;
    bool has2 = (x + 2 < W);

    half2 r0[8], r1[8], r2[8];               // rec(x), rec(x+1), rec(x+2 clamped)
#pragma unroll
    for (int j = 0; j < 8; j++) {
        float2 a = __ldcs((const float2*)(src + (size_t)(2 * j)     * HW + lin));  // fa(x), fa(x+1)
        float2 b = __ldcs((const float2*)(src + (size_t)(2 * j + 1) * HW + lin));  // fb(x), fb(x+1)
        float a2 = has2 ? __ldcs(src + (size_t)(2 * j)     * HW + lin + 2) : a.y;
        float b2 = has2 ? __ldcs(src + (size_t)(2 * j + 1) * HW + lin + 2) : b.y;
        r0[j] = __floats2half2_rn(a.x, b.x);
        r1[j] = __floats2half2_rn(a.y, b.y);
        r2[j] = __floats2half2_rn(a2,  b2);
    }
    // entry(x) = [r0 | r1] at lin*4 ; entry(x+1) = [r1 | r2] at (lin+1)*4
    uint4 o;
    const unsigned* p0 = reinterpret_cast<const unsigned*>(r0);
    const unsigned* p1 = reinterpret_cast<const unsigned*>(r1);
    const unsigned* p2 = reinterpret_cast<const unsigned*>(r2);
    o.x = p0[0]; o.y = p0[1]; o.z = p0[2]; o.w = p0[3]; dst[(size_t)lin * 4 + 0] = o;
    o.x = p0[4]; o.y = p0[5]; o.z = p0[6]; o.w = p0[7]; dst[(size_t)lin * 4 + 1] = o;
    o.x = p1[0]; o.y = p1[1]; o.z = p1[2]; o.w = p1[3]; dst[(size_t)lin * 4 + 2] = o;
    o.x = p1[4]; o.y = p1[5]; o.z = p1[6]; o.w = p1[7]; dst[(size_t)lin * 4 + 3] = o;
    o.x = p1[0]; o.y = p1[1]; o.z = p1[2]; o.w = p1[3]; dst[(size_t)lin * 4 + 4] = o;
    o.x = p1[4]; o.y = p1[5]; o.z = p1[6]; o.w = p1[7]; dst[(size_t)lin * 4 + 5] = o;
    o.x = p2[0]; o.y = p2[1]; o.z = p2[2]; o.w = p2[3]; dst[(size_t)lin * 4 + 6] = o;
    o.x = p2[4]; o.y = p2[5]; o.z = p2[6]; o.w = p2[7]; dst[(size_t)lin * 4 + 7] = o;
}

// ---------------------------------------------------------------------------
// Per-level phase A. PAIR=false: plain records (level 1), x-clamp in gather.
// PAIR=true: pair entries, x-clamp baked into layout; 4 lanes (side,h) read a
// contiguous 64B-aligned span per row -> guaranteed single wavefront.
// ---------------------------------------------------------------------------
template <int W, bool PAIR>
__device__ __forceinline__ void level_load(const uint4* __restrict__ base,
                                           float ix, float iy, int h, int side,
                                           uint4& u0, uint4& u1,
                                           float& wxs, half2& w0h, half2& w1h) {
    const float Wf = (float)W;
    float cx = fminf(fmaxf(ix, 0.0f), Wf - 1.0f);
    float cy = fminf(fmaxf(iy, 0.0f), Wf - 1.0f);
    float x0f = floorf(cx);
    float y0f = floorf(cy);
    float wx = cx - x0f;
    float wy = cy - y0f;
    int x0 = (int)x0f;
    int y0 = (int)y0f;
    int y1 = min(y0 + 1, W - 1);

    wxs = side ? wx : (1.0f - wx);
    w0h = __float2half2_rn(1.0f - wy);
    w1h = __float2half2_rn(wy);

    if (PAIR) {
        u0 = __ldg(base + ((y0 * W + x0) * 4 + side * 2 + h));
        u1 = __ldg(base + ((y1 * W + x0) * 4 + side * 2 + h));
    } else {
        int xs = side ? min(x0 + 1, W - 1) : x0;
        u0 = __ldg(base + ((y0 * W + xs) * 2 + h));
        u1 = __ldg(base + ((y1 * W + xs) * 2 + h));
    }
}

// ---------------------------------------------------------------------------
// Gather: one thread per (pixel, feature-half, x-side). t = p*4 + side*2 + h.
// Phase A: all 8 loads front-batched (MLP=8), derived-coordinate chain.
// Phase B: half2 row-fold per level, fp32 accumulate scaled by x-side weight.
// Epilogue: shfl.xor(2) folds x-sides; side-0 lanes store 8 features.
// ---------------------------------------------------------------------------
__global__ void __launch_bounds__(256) gather_kernel(const float* __restrict__ grid,
                                                     float* __restrict__ out) {
    int t = blockIdx.x * blockDim.x + threadIdx.x;
    int p    = t >> 2;           // pixel 0..2^20-1
    int h    = t & 1;            // feature half
    int side = (t >> 1) & 1;     // x corner side

    float2 g = __ldg((const float2*)grid + p);

    // Unclamped level-1 coords; per-level derived by ix' = 0.5*ix - 0.25.
    float ix = ((g.x + 1.0f) * (float)W1 - 1.0f) * 0.5f;
    float iy = ((g.y + 1.0f) * (float)W1 - 1.0f) * 0.5f;

    uint4 u0[4], u1[4];
    half2 w0h[4], w1h[4];
    float wxs[4];

    level_load<W1, false>(g_p1, ix, iy, h, side, u0[0], u1[0], wxs[0], w0h[0], w1h[0]);
    ix = ix * 0.5f - 0.25f;  iy = iy * 0.5f - 0.25f;
    level_load<W2, true >(g_q2, ix, iy, h, side, u0[1], u1[1], wxs[1], w0h[1], w1h[1]);
    ix = ix * 0.5f - 0.25f;  iy = iy * 0.5f - 0.25f;
    level_load<W3, true >(g_q3, ix, iy, h, side, u0[2], u1[2], wxs[2], w0h[2], w1h[2]);
    ix = ix * 0.5f - 0.25f;  iy = iy * 0.5f - 0.25f;
    level_load<W4, true >(g_q4, ix, iy, h, side, u0[3], u1[3], wxs[3], w0h[3], w1h[3]);

    float acc[8];
#pragma unroll
    for (int j = 0; j < 8; j++) acc[j] = 0.0f;

#pragma unroll
    for (int L = 0; L < 4; L++) {
        const half2* v0 = reinterpret_cast<const half2*>(&u0[L]);
        const half2* v1 = reinterpret_cast<const half2*>(&u1[L]);
        float ws = wxs[L];
#pragma unroll
        for (int k = 0; k < 4; k++) {
            half2 tk = __hfma2(v1[k], w1h[L], __hmul2(v0[k], w0h[L]));
            float2 tf = __half22float2(tk);
            acc[2 * k]     = fmaf(tf.x, ws, acc[2 * k]);
            acc[2 * k + 1] = fmaf(tf.y, ws, acc[2 * k + 1]);
        }
    }

    // Fold x-sides: lane (p, side, h) <-> (p, side^1, h)
#pragma unroll
    for (int j = 0; j < 8; j++)
        acc[j] += __shfl_xor_sync(0xffffffffu, acc[j], 2);

    if (side == 0) {
        int b  = p >> 18;        // batch
        int hw = p & (HWO - 1);
        // out layout: (B, F, Ho, Wo); this lane owns features 8h..8h+7
        size_t base = ((size_t)(b * FEAT + h * 8) << 18) | (unsigned)hw;
#pragma unroll
        for (int j = 0; j < 8; j++)
            __stcs(out + base + (size_t)j * HWO, acc[j]);  // streaming stores
    }
}

extern "C" void kernel_launch(void* const* d_in, const int* in_sizes, int n_in,
                              void* d_out, int out_size) {
    const float* x    = (const float*)d_in[0];   // (4, 512, 512, 2)
    const float* tex1 = (const float*)d_in[1];   // (16, 1024, 1024)
    const float* tex2 = (const float*)d_in[2];   // (16, 512, 512)
    const float* tex3 = (const float*)d_in[3];   // (16, 256, 256)
    const float* tex4 = (const float*)d_in[4];   // (16, 128, 128)
    float* out = (float*)d_out;                  // (4, 16, 512, 512)

    // Fused repack: level 1 plain (pairs of texels) + levels 2-4 pair entries.
    const int total_threads = N1 / 2 + N2 / 2 + N3 / 2 + N4 / 2;  // 696,320
    repack_fused_kernel<<<(total_threads + 255) / 256, 256>>>(tex1, tex2, tex3, tex4);

    // Gather + blend + sum levels. One thread per (pixel, half, side).
    gather_kernel<<<(4 * NPIX) / 256, 256>>>(x, out);
}